// round 9
// baseline (speedup 1.0000x reference)
#include <cuda_runtime.h>
#include <cstdint>

#define NMAX 100000
#define FDIM 128
#define CAP  64     // per-node bucket capacity (mean in-deg 6.4; P(>64) ~ 0)

// Scratch (__device__ globals; no cudaMalloc allowed)
__device__ int   g_cnt[NMAX];
__device__ float g_dinv[NMAX];
__device__ int   g_bucket[(size_t)NMAX * CAP];
__device__ float g_xw[(size_t)NMAX * FDIM];

// ---- per-block dtype detection (int64 vs silently-downcast int32) ----
__device__ __forceinline__ int detect_is64_block(const void* ei, int E, int N) {
    __shared__ int s_is64;
    if (threadIdx.x < 32) {
        int n = E < 32 ? E : 32;
        int ok = 1;
        if ((int)threadIdx.x < n) {
            long long v = ((const long long*)ei)[threadIdx.x];
            ok = (v >= 0 && v < (long long)N);
        }
        unsigned m = __ballot_sync(0xffffffffu, ok);
        if (threadIdx.x == 0) s_is64 = (m == 0xffffffffu);
    }
    __syncthreads();
    return s_is64;
}
__device__ __forceinline__ int load_idx(const void* ei, size_t i, int is64) {
    if (is64) return (int)((const long long*)ei)[i];
    return ((const int*)ei)[i];
}

__global__ void k_fill(const void* __restrict__ ei, int E, int N) {
    int is64 = detect_is64_block(ei, E, N);
    int e = blockIdx.x * blockDim.x + threadIdx.x;
    if (e < E) {
        int r = load_idx(ei, (size_t)e, is64);
        int c = load_idx(ei, (size_t)E + e, is64);
        int pos = atomicAdd(&g_cnt[c], 1);
        if (pos < CAP) g_bucket[(size_t)c * CAP + pos] = r;
    }
}

__global__ void k_dinv(int N) {
    int i = blockIdx.x * blockDim.x + threadIdx.x;
    if (i < N) g_dinv[i] = rsqrtf((float)g_cnt[i] + 2.0f);  // improved fill 2.0
}

// ---- GEMM: g_xw = x @ W. 128x128 tile, 8x8 per thread, f32x2 FMA ----
__global__ __launch_bounds__(256) void k_gemm(
    const float* __restrict__ x, const float* __restrict__ W, int N)
{
    __shared__ __align__(16) float xs_t[32][132];  // [k][row 0..127]
    __shared__ __align__(16) float ws[32][128];    // [k][col]

    int t  = threadIdx.x;
    int tx = t & 15;                 // col group: cols tx*8 .. tx*8+7
    int ty = t >> 4;                 // row group: rows ty*8 .. ty*8+7
    int rowBase = blockIdx.x * 128;

    // acc[j][c]: j = row pair (rows ty*8+2j, +2j+1), c = col tx*8+c
    unsigned long long acc[4][8];
#pragma unroll
    for (int j = 0; j < 4; j++)
#pragma unroll
        for (int c = 0; c < 8; c++) acc[j][c] = 0ULL;

    for (int k0 = 0; k0 < 128; k0 += 32) {
        __syncthreads();
        // W tile: 32 k x 128 c = 1024 float4 / 256 thr
#pragma unroll
        for (int i = 0; i < 4; i++) {
            int j = t + i * 256;
            int k = j >> 5;
            int c = (j & 31) << 2;
            float4 v = *(const float4*)&W[(size_t)(k0 + k) * 128 + c];
            ws[k][c] = v.x; ws[k][c + 1] = v.y; ws[k][c + 2] = v.z; ws[k][c + 3] = v.w;
        }
        // x tile: 128 rows x 32 k = 1024 float4 / 256 thr, transposed
#pragma unroll
        for (int i = 0; i < 4; i++) {
            int j  = t + i * 256;
            int r  = j >> 3;              // 0..127
            int kk = (j & 7) << 2;        // 0..28
            int row = rowBase + r;
            float4 v = make_float4(0.f, 0.f, 0.f, 0.f);
            if (row < N) v = *(const float4*)&x[(size_t)row * 128 + k0 + kk];
            xs_t[kk][r] = v.x; xs_t[kk + 1][r] = v.y;
            xs_t[kk + 2][r] = v.z; xs_t[kk + 3][r] = v.w;
        }
        __syncthreads();

#pragma unroll 4
        for (int k = 0; k < 32; k++) {
            float4 bv0 = *(const float4*)&ws[k][tx << 3];
            float4 bv1 = *(const float4*)&ws[k][(tx << 3) + 4];
            unsigned long long bd[8];
            asm("mov.b64 %0, {%1,%1};" : "=l"(bd[0]) : "f"(bv0.x));
            asm("mov.b64 %0, {%1,%1};" : "=l"(bd[1]) : "f"(bv0.y));
            asm("mov.b64 %0, {%1,%1};" : "=l"(bd[2]) : "f"(bv0.z));
            asm("mov.b64 %0, {%1,%1};" : "=l"(bd[3]) : "f"(bv0.w));
            asm("mov.b64 %0, {%1,%1};" : "=l"(bd[4]) : "f"(bv1.x));
            asm("mov.b64 %0, {%1,%1};" : "=l"(bd[5]) : "f"(bv1.y));
            asm("mov.b64 %0, {%1,%1};" : "=l"(bd[6]) : "f"(bv1.z));
            asm("mov.b64 %0, {%1,%1};" : "=l"(bd[7]) : "f"(bv1.w));
            unsigned long long ap[4];
#pragma unroll
            for (int j = 0; j < 4; j++)
                ap[j] = *(const unsigned long long*)&xs_t[k][ty * 8 + 2 * j];
#pragma unroll
            for (int j = 0; j < 4; j++)
#pragma unroll
                for (int c = 0; c < 8; c++)
                    asm("fma.rn.f32x2 %0, %1, %2, %0;"
                        : "+l"(acc[j][c]) : "l"(ap[j]), "l"(bd[c]));
        }
    }

    // epilogue: unpack row pairs, coalesced float4 stores
#pragma unroll
    for (int j = 0; j < 4; j++) {
        float lo[8], hi[8];
#pragma unroll
        for (int c = 0; c < 8; c++)
            asm("mov.b64 {%0,%1}, %2;" : "=f"(lo[c]), "=f"(hi[c]) : "l"(acc[j][c]));
        int row0 = rowBase + ty * 8 + 2 * j;
        if (row0 < N) {
            float4* p = (float4*)&g_xw[(size_t)row0 * 128 + (tx << 3)];
            p[0] = make_float4(lo[0], lo[1], lo[2], lo[3]);
            p[1] = make_float4(lo[4], lo[5], lo[6], lo[7]);
        }
        if (row0 + 1 < N) {
            float4* p = (float4*)&g_xw[(size_t)(row0 + 1) * 128 + (tx << 3)];
            p[0] = make_float4(hi[0], hi[1], hi[2], hi[3]);
            p[1] = make_float4(hi[4], hi[5], hi[6], hi[7]);
        }
    }
}

// ---- aggregate: warp per node, bucket walk (proven R5 form) ----
__global__ __launch_bounds__(256) void k_agg(
    const float* __restrict__ b, float* __restrict__ out, int N)
{
    int c = (int)((blockIdx.x * (unsigned)blockDim.x + threadIdx.x) >> 5);
    int lane = threadIdx.x & 31;
    if (c >= N) return;
    int cnt = g_cnt[c];
    int m = cnt < CAP ? cnt : CAP;
    float dc = g_dinv[c];
    int col = lane << 2;
    const int* bk = &g_bucket[(size_t)c * CAP];

    float4 a0 = make_float4(0.f, 0.f, 0.f, 0.f);
    float4 a1 = make_float4(0.f, 0.f, 0.f, 0.f);
    int i = 0;
    for (; i + 4 <= m; i += 4) {
        int r0 = bk[i], r1 = bk[i+1], r2 = bk[i+2], r3 = bk[i+3];
        float n0 = g_dinv[r0], n1 = g_dinv[r1], n2 = g_dinv[r2], n3 = g_dinv[r3];
        float4 v0 = *(const float4*)&g_xw[(size_t)r0 * 128 + col];
        float4 v1 = *(const float4*)&g_xw[(size_t)r1 * 128 + col];
        float4 v2 = *(const float4*)&g_xw[(size_t)r2 * 128 + col];
        float4 v3 = *(const float4*)&g_xw[(size_t)r3 * 128 + col];
        a0.x += n0*v0.x + n1*v1.x;  a1.x += n2*v2.x + n3*v3.x;
        a0.y += n0*v0.y + n1*v1.y;  a1.y += n2*v2.y + n3*v3.y;
        a0.z += n0*v0.z + n1*v1.z;  a1.z += n2*v2.z + n3*v3.z;
        a0.w += n0*v0.w + n1*v1.w;  a1.w += n2*v2.w + n3*v3.w;
    }
    for (; i < m; i++) {
        int r0 = bk[i];
        float n0 = g_dinv[r0];
        float4 v0 = *(const float4*)&g_xw[(size_t)r0 * 128 + col];
        a0.x += n0*v0.x; a0.y += n0*v0.y; a0.z += n0*v0.z; a0.w += n0*v0.w;
    }
    a0.x += a1.x; a0.y += a1.y; a0.z += a1.z; a0.w += a1.w;

    float s = 2.0f * dc * dc;
    float4 xwc = *(const float4*)&g_xw[(size_t)c * 128 + col];
    float4 bb  = *(const float4*)&b[col];
    float4 o;
    o.x = fmaf(dc, a0.x, fmaf(s, xwc.x, bb.x));
    o.y = fmaf(dc, a0.y, fmaf(s, xwc.y, bb.y));
    o.z = fmaf(dc, a0.z, fmaf(s, xwc.z, bb.z));
    o.w = fmaf(dc, a0.w, fmaf(s, xwc.w, bb.w));
    *(float4*)&out[(size_t)c * 128 + col] = o;
}

// ---------------- launch: GEMM forked onto a side stream ----------------
struct Ctx {
    cudaStream_t s;
    cudaEvent_t  fork, join;
    void*        cntAddr;
    bool         ok;
};
static Ctx& ctx() {
    static Ctx c = [] {
        Ctx c{};
        c.ok = true;
        if (cudaStreamCreateWithFlags(&c.s, cudaStreamNonBlocking) != cudaSuccess) c.ok = false;
        if (cudaEventCreateWithFlags(&c.fork, cudaEventDisableTiming) != cudaSuccess) c.ok = false;
        if (cudaEventCreateWithFlags(&c.join, cudaEventDisableTiming) != cudaSuccess) c.ok = false;
        if (cudaGetSymbolAddress(&c.cntAddr, g_cnt) != cudaSuccess) c.ok = false;
        return c;
    }();
    return c;
}

extern "C" void kernel_launch(void* const* d_in, const int* in_sizes, int n_in,
                              void* d_out, int out_size)
{
    const float* x  = (const float*)d_in[0];
    const void*  ei = (const void*)d_in[1];
    const float* W  = (const float*)d_in[2];
    const float* b  = (const float*)d_in[3];
    float* out = (float*)d_out;

    int N = in_sizes[0] / FDIM;   // 100000
    int E = in_sizes[1] / 2;      // 640000

    Ctx& c = ctx();

    if (c.ok) {
        // fork GEMM onto side stream (independent of bucket build)
        cudaEventRecord(c.fork, 0);
        cudaStreamWaitEvent(c.s, c.fork, 0);
        k_gemm<<<(N + 127) / 128, 256, 0, c.s>>>(x, W, N);
        cudaEventRecord(c.join, c.s);

        // main: bucket build + norms (hidden under GEMM)
        cudaMemsetAsync(c.cntAddr, 0, (size_t)N * sizeof(int), 0);
        k_fill<<<(E + 255) / 256, 256>>>(ei, E, N);
        k_dinv<<<(N + 255) / 256, 256>>>(N);

        cudaStreamWaitEvent(0, c.join, 0);
        k_agg<<<((N * 32) + 255) / 256, 256>>>(b, out, N);
    } else {
        cudaMemsetAsync(c.cntAddr, 0, (size_t)N * sizeof(int), 0);
        k_fill<<<(E + 255) / 256, 256>>>(ei, E, N);
        k_dinv<<<(N + 255) / 256, 256>>>(N);
        k_gemm <<<(N + 127) / 128, 256>>>(x, W, N);
        k_agg  <<<((N * 32) + 255) / 256, 256>>>(b, out, N);
    }
}

// round 10
// speedup vs baseline: 1.1694x; 1.1694x over previous
#include <cuda_runtime.h>
#include <cstdint>

#define NMAX 100000
#define FDIM 128
#define CAP  64     // per-node bucket capacity (mean in-deg 6.4; P(>64) ~ 0)

// Scratch (__device__ globals; no cudaMalloc allowed)
__device__ int   g_cnt[NMAX];
__device__ float g_dinv[NMAX];
__device__ int   g_bucket[(size_t)NMAX * CAP];
__device__ float g_xw[(size_t)NMAX * FDIM];

// ---- per-block dtype detection (int64 vs silently-downcast int32) ----
__device__ __forceinline__ int detect_is64_block(const void* ei, int E, int N) {
    __shared__ int s_is64;
    if (threadIdx.x < 32) {
        int n = E < 32 ? E : 32;
        int ok = 1;
        if ((int)threadIdx.x < n) {
            long long v = ((const long long*)ei)[threadIdx.x];
            ok = (v >= 0 && v < (long long)N);
        }
        unsigned m = __ballot_sync(0xffffffffu, ok);
        if (threadIdx.x == 0) s_is64 = (m == 0xffffffffu);
    }
    __syncthreads();
    return s_is64;
}
__device__ __forceinline__ int load_idx(const void* ei, size_t i, int is64) {
    if (is64) return (int)((const long long*)ei)[i];
    return ((const int*)ei)[i];
}

__global__ void k_fill(const void* __restrict__ ei, int E, int N) {
    int is64 = detect_is64_block(ei, E, N);
    int e = blockIdx.x * blockDim.x + threadIdx.x;
    if (e < E) {
        int r = load_idx(ei, (size_t)e, is64);
        int c = load_idx(ei, (size_t)E + e, is64);
        int pos = atomicAdd(&g_cnt[c], 1);
        if (pos < CAP) g_bucket[(size_t)c * CAP + pos] = r;
    }
}

__global__ void k_dinv(int N) {
    int i = blockIdx.x * blockDim.x + threadIdx.x;
    if (i < N) g_dinv[i] = rsqrtf((float)g_cnt[i] + 2.0f);  // improved fill 2.0
}

// ---- GEMM: g_xw = x @ W. 64x128 tile, 8x4/thread, f32x2 FMA (R5/R8 proven) ----
__global__ __launch_bounds__(256) void k_gemm(
    const float* __restrict__ x, const float* __restrict__ W, int N)
{
    __shared__ float xs_t[32][66];   // [k][row], stride 66
    __shared__ float ws[32][128];

    int t  = threadIdx.x;
    int tx = t & 31;                 // cols tx*4 .. tx*4+3
    int ty = t >> 5;                 // rows ty*8 .. ty*8+7
    int rowBase = blockIdx.x * 64;

    unsigned long long acc[4][4];
#pragma unroll
    for (int j = 0; j < 4; j++)
#pragma unroll
        for (int c = 0; c < 4; c++) acc[j][c] = 0ULL;

    for (int k0 = 0; k0 < 128; k0 += 32) {
        __syncthreads();
#pragma unroll
        for (int i = 0; i < 4; i++) {           // W tile: 32k x 128c
            int j = t + i * 256;
            int k = j >> 5;
            int c = (j & 31) << 2;
            float4 v = *(const float4*)&W[(size_t)(k0 + k) * 128 + c];
            ws[k][c] = v.x; ws[k][c + 1] = v.y; ws[k][c + 2] = v.z; ws[k][c + 3] = v.w;
        }
#pragma unroll
        for (int i = 0; i < 2; i++) {           // x tile -> transposed
            int j  = t + i * 256;
            int r  = j >> 3;
            int kk = (j & 7) << 2;
            int row = rowBase + r;
            float4 v = make_float4(0.f, 0.f, 0.f, 0.f);
            if (row < N) v = *(const float4*)&x[(size_t)row * 128 + k0 + kk];
            xs_t[kk][r] = v.x; xs_t[kk + 1][r] = v.y;
            xs_t[kk + 2][r] = v.z; xs_t[kk + 3][r] = v.w;
        }
        __syncthreads();

#pragma unroll
        for (int k = 0; k < 32; k++) {
            float4 bv = *(const float4*)&ws[k][tx << 2];
            unsigned long long bd[4];
            asm("mov.b64 %0, {%1,%1};" : "=l"(bd[0]) : "f"(bv.x));
            asm("mov.b64 %0, {%1,%1};" : "=l"(bd[1]) : "f"(bv.y));
            asm("mov.b64 %0, {%1,%1};" : "=l"(bd[2]) : "f"(bv.z));
            asm("mov.b64 %0, {%1,%1};" : "=l"(bd[3]) : "f"(bv.w));
#pragma unroll
            for (int j = 0; j < 4; j++) {
                unsigned long long ap =
                    *(const unsigned long long*)&xs_t[k][ty * 8 + 2 * j];
#pragma unroll
                for (int c = 0; c < 4; c++)
                    asm("fma.rn.f32x2 %0, %1, %2, %0;"
                        : "+l"(acc[j][c]) : "l"(ap), "l"(bd[c]));
            }
        }
    }

#pragma unroll
    for (int j = 0; j < 4; j++) {
        float lo[4], hi[4];
#pragma unroll
        for (int c = 0; c < 4; c++)
            asm("mov.b64 {%0,%1}, %2;" : "=f"(lo[c]), "=f"(hi[c]) : "l"(acc[j][c]));
        int row0 = rowBase + ty * 8 + 2 * j;
        if (row0 < N)
            *(float4*)&g_xw[(size_t)row0 * 128 + (tx << 2)] =
                make_float4(lo[0], lo[1], lo[2], lo[3]);
        if (row0 + 1 < N)
            *(float4*)&g_xw[(size_t)(row0 + 1) * 128 + (tx << 2)] =
                make_float4(hi[0], hi[1], hi[2], hi[3]);
    }
}

// ---- aggregate: TWO nodes per warp, predicated interleaved gathers ----
__global__ __launch_bounds__(256) void k_agg2(
    const float* __restrict__ b, float* __restrict__ out, int N)
{
    int warp = (int)((blockIdx.x * (unsigned)blockDim.x + threadIdx.x) >> 5);
    int lane = threadIdx.x & 31;
    int c0 = warp * 2;
    int c1 = warp * 2 + 1;
    if (c0 >= N) return;
    bool has1 = (c1 < N);

    int cnt0 = g_cnt[c0];
    int cnt1 = has1 ? g_cnt[c1] : 0;
    int m0 = cnt0 < CAP ? cnt0 : CAP;
    int m1 = cnt1 < CAP ? cnt1 : CAP;
    float dc0 = g_dinv[c0];
    float dc1 = has1 ? g_dinv[c1] : 0.f;
    int col = lane << 2;
    const int* bk0 = &g_bucket[(size_t)c0 * CAP];
    const int* bk1 = &g_bucket[(size_t)c1 * CAP];

    float4 a0 = make_float4(0.f, 0.f, 0.f, 0.f);
    float4 a1 = make_float4(0.f, 0.f, 0.f, 0.f);

    int mm = m0 > m1 ? m0 : m1;
    for (int j = 0; j < mm; j += 2) {
        // predicated slot fetch: invalid -> weight 0, safe row (c0/c1)
        int  i00 = (j     < m0) ? bk0[j]     : c0;
        int  i01 = (j + 1 < m0) ? bk0[j + 1] : c0;
        int  i10 = (j     < m1) ? bk1[j]     : c0;
        int  i11 = (j + 1 < m1) ? bk1[j + 1] : c0;
        float w00 = (j     < m0) ? g_dinv[i00] : 0.f;
        float w01 = (j + 1 < m0) ? g_dinv[i01] : 0.f;
        float w10 = (j     < m1) ? g_dinv[i10] : 0.f;
        float w11 = (j + 1 < m1) ? g_dinv[i11] : 0.f;
        // 4 independent row gathers in flight
        float4 v00 = *(const float4*)&g_xw[(size_t)i00 * 128 + col];
        float4 v01 = *(const float4*)&g_xw[(size_t)i01 * 128 + col];
        float4 v10 = *(const float4*)&g_xw[(size_t)i10 * 128 + col];
        float4 v11 = *(const float4*)&g_xw[(size_t)i11 * 128 + col];
        a0.x += w00 * v00.x + w01 * v01.x;
        a0.y += w00 * v00.y + w01 * v01.y;
        a0.z += w00 * v00.z + w01 * v01.z;
        a0.w += w00 * v00.w + w01 * v01.w;
        a1.x += w10 * v10.x + w11 * v11.x;
        a1.y += w10 * v10.y + w11 * v11.y;
        a1.z += w10 * v10.z + w11 * v11.z;
        a1.w += w10 * v10.w + w11 * v11.w;
    }

    float4 bb = *(const float4*)&b[col];
    {
        float s = 2.0f * dc0 * dc0;
        float4 xwc = *(const float4*)&g_xw[(size_t)c0 * 128 + col];
        float4 o;
        o.x = fmaf(dc0, a0.x, fmaf(s, xwc.x, bb.x));
        o.y = fmaf(dc0, a0.y, fmaf(s, xwc.y, bb.y));
        o.z = fmaf(dc0, a0.z, fmaf(s, xwc.z, bb.z));
        o.w = fmaf(dc0, a0.w, fmaf(s, xwc.w, bb.w));
        *(float4*)&out[(size_t)c0 * 128 + col] = o;
    }
    if (has1) {
        float s = 2.0f * dc1 * dc1;
        float4 xwc = *(const float4*)&g_xw[(size_t)c1 * 128 + col];
        float4 o;
        o.x = fmaf(dc1, a1.x, fmaf(s, xwc.x, bb.x));
        o.y = fmaf(dc1, a1.y, fmaf(s, xwc.y, bb.y));
        o.z = fmaf(dc1, a1.z, fmaf(s, xwc.z, bb.z));
        o.w = fmaf(dc1, a1.w, fmaf(s, xwc.w, bb.w));
        *(float4*)&out[(size_t)c1 * 128 + col] = o;
    }
}

// ---------------- launch: GEMM forked onto a side stream ----------------
struct Ctx {
    cudaStream_t s;
    cudaEvent_t  fork, join;
    void*        cntAddr;
    bool         ok;
};
static Ctx& ctx() {
    static Ctx c = [] {
        Ctx c{};
        c.ok = true;
        if (cudaStreamCreateWithFlags(&c.s, cudaStreamNonBlocking) != cudaSuccess) c.ok = false;
        if (cudaEventCreateWithFlags(&c.fork, cudaEventDisableTiming) != cudaSuccess) c.ok = false;
        if (cudaEventCreateWithFlags(&c.join, cudaEventDisableTiming) != cudaSuccess) c.ok = false;
        if (cudaGetSymbolAddress(&c.cntAddr, g_cnt) != cudaSuccess) c.ok = false;
        return c;
    }();
    return c;
}

extern "C" void kernel_launch(void* const* d_in, const int* in_sizes, int n_in,
                              void* d_out, int out_size)
{
    const float* x  = (const float*)d_in[0];
    const void*  ei = (const void*)d_in[1];
    const float* W  = (const float*)d_in[2];
    const float* b  = (const float*)d_in[3];
    float* out = (float*)d_out;

    int N = in_sizes[0] / FDIM;   // 100000
    int E = in_sizes[1] / 2;      // 640000
    int nWarps = (N + 1) / 2;     // 2 nodes per warp

    Ctx& c = ctx();

    if (c.ok) {
        // fork GEMM onto side stream (independent of bucket build)
        cudaEventRecord(c.fork, 0);
        cudaStreamWaitEvent(c.s, c.fork, 0);
        k_gemm<<<(N + 63) / 64, 256, 0, c.s>>>(x, W, N);
        cudaEventRecord(c.join, c.s);

        // main: bucket build + norms (hidden under GEMM)
        cudaMemsetAsync(c.cntAddr, 0, (size_t)N * sizeof(int), 0);
        k_fill<<<(E + 255) / 256, 256>>>(ei, E, N);
        k_dinv<<<(N + 255) / 256, 256>>>(N);

        cudaStreamWaitEvent(0, c.join, 0);
        k_agg2<<<(nWarps * 32 + 255) / 256, 256>>>(b, out, N);
    } else {
        cudaMemsetAsync(c.cntAddr, 0, (size_t)N * sizeof(int), 0);
        k_fill<<<(E + 255) / 256, 256>>>(ei, E, N);
        k_dinv<<<(N + 255) / 256, 256>>>(N);
        k_gemm <<<(N + 63) / 64, 256>>>(x, W, N);
        k_agg2 <<<(nWarps * 32 + 255) / 256, 256>>>(b, out, N);
    }
}

// round 11
// speedup vs baseline: 1.2740x; 1.0895x over previous
#include <cuda_runtime.h>
#include <cuda_bf16.h>
#include <cstdint>

#define NMAX 100000
#define FDIM 128
#define CAP  64

// Scratch (__device__ globals; no cudaMalloc allowed)
__device__ int   g_cnt[NMAX];
__device__ float g_dinv[NMAX];
__device__ int   g_bucket[(size_t)NMAX * CAP];
__device__ float g_xw[(size_t)NMAX * FDIM];
__device__ __align__(16) __nv_bfloat16 g_wt_hi[16384];  // W^T hi [n][k]
__device__ __align__(16) __nv_bfloat16 g_wt_lo[16384];  // W^T lo [n][k]

// ---- per-block dtype detection (int64 vs silently-downcast int32) ----
__device__ __forceinline__ int detect_is64_block(const void* ei, int E, int N) {
    __shared__ int s_is64;
    if (threadIdx.x < 32) {
        int n = E < 32 ? E : 32;
        int ok = 1;
        if ((int)threadIdx.x < n) {
            long long v = ((const long long*)ei)[threadIdx.x];
            ok = (v >= 0 && v < (long long)N);
        }
        unsigned m = __ballot_sync(0xffffffffu, ok);
        if (threadIdx.x == 0) s_is64 = (m == 0xffffffffu);
    }
    __syncthreads();
    return s_is64;
}
__device__ __forceinline__ int load_idx(const void* ei, size_t i, int is64) {
    if (is64) return (int)((const long long*)ei)[i];
    return ((const int*)ei)[i];
}

__global__ void k_fill(const void* __restrict__ ei, int E, int N) {
    int is64 = detect_is64_block(ei, E, N);
    int e = blockIdx.x * blockDim.x + threadIdx.x;
    if (e < E) {
        int r = load_idx(ei, (size_t)e, is64);
        int c = load_idx(ei, (size_t)E + e, is64);
        int pos = atomicAdd(&g_cnt[c], 1);
        if (pos < CAP) g_bucket[(size_t)c * CAP + pos] = r;
    }
}

__global__ void k_dinv(int N) {
    int i = blockIdx.x * blockDim.x + threadIdx.x;
    if (i < N) g_dinv[i] = rsqrtf((float)g_cnt[i] + 2.0f);
}

// ---- prep: W^T -> bf16 hi/lo ----
__global__ void k_prepw(const float* __restrict__ W) {
    int idx = blockIdx.x * blockDim.x + threadIdx.x;   // 0..16383
    int n = idx >> 7, k = idx & 127;
    float w = W[(size_t)k * 128 + n];
    __nv_bfloat16 hi = __float2bfloat16(w);
    __nv_bfloat16 lo = __float2bfloat16(w - __bfloat162float(hi));
    g_wt_hi[n * 128 + k] = hi;
    g_wt_lo[n * 128 + k] = lo;
}

// ---- mma helpers ----
__device__ __forceinline__ uint32_t smem_u32(const void* p) {
    uint32_t a;
    asm("{ .reg .u64 t; cvta.to.shared.u64 t, %1; cvt.u32.u64 %0, t; }"
        : "=r"(a) : "l"(p));
    return a;
}
__device__ __forceinline__ void ldmx4(uint32_t& r0, uint32_t& r1, uint32_t& r2,
                                      uint32_t& r3, uint32_t addr) {
    asm volatile("ldmatrix.sync.aligned.m8n8.x4.shared.b16 {%0,%1,%2,%3}, [%4];"
                 : "=r"(r0), "=r"(r1), "=r"(r2), "=r"(r3) : "r"(addr));
}
__device__ __forceinline__ void mma_bf16(float* c, uint32_t a0, uint32_t a1,
                                         uint32_t a2, uint32_t a3,
                                         uint32_t b0, uint32_t b1) {
    asm volatile(
        "mma.sync.aligned.m16n8k16.row.col.f32.bf16.bf16.f32 "
        "{%0,%1,%2,%3}, {%4,%5,%6,%7}, {%8,%9}, {%0,%1,%2,%3};"
        : "+f"(c[0]), "+f"(c[1]), "+f"(c[2]), "+f"(c[3])
        : "r"(a0), "r"(a1), "r"(a2), "r"(a3), "r"(b0), "r"(b1));
}

// ---- tensor-core GEMM: g_xw = x @ W via 3-term bf16 split ----
#define SPITCH_B 272                       // bytes per smem row (136 bf16)
#define SARR     (128 * SPITCH_B)          // 34816 B per array
#define SMEM_MMA (4 * SARR)                // 139264 B

__global__ __launch_bounds__(256, 1) void k_gemm_mma(const float* __restrict__ x, int N)
{
    extern __shared__ char sm[];
    char* a_hi = sm;
    char* a_lo = sm + SARR;
    char* b_hi = sm + 2 * SARR;
    char* b_lo = sm + 3 * SARR;

    int t = threadIdx.x, wid = t >> 5, lane = t & 31;
    int tileBase = blockIdx.x * 128;

    // convert x tile (128x128) to bf16 hi/lo, padded rows
#pragma unroll
    for (int i = 0; i < 16; i++) {
        int widx = i * 256 + t;            // float4 index, 0..4095
        int row  = widx >> 5;
        int c4   = (widx & 31) << 2;       // float col, mult of 4
        int grow = tileBase + row;
        float4 v = make_float4(0.f, 0.f, 0.f, 0.f);
        if (grow < N) v = *(const float4*)(x + (size_t)grow * 128 + c4);
        __nv_bfloat16 hx = __float2bfloat16(v.x), hy = __float2bfloat16(v.y);
        __nv_bfloat16 hz = __float2bfloat16(v.z), hw = __float2bfloat16(v.w);
        __nv_bfloat16 lx = __float2bfloat16(v.x - __bfloat162float(hx));
        __nv_bfloat16 ly = __float2bfloat16(v.y - __bfloat162float(hy));
        __nv_bfloat16 lz = __float2bfloat16(v.z - __bfloat162float(hz));
        __nv_bfloat16 lw = __float2bfloat16(v.w - __bfloat162float(hw));
        __nv_bfloat162 h01(hx, hy), h23(hz, hw), l01(lx, ly), l23(lz, lw);
        uint32_t byte = (uint32_t)row * SPITCH_B + c4 * 2;
        *(uint2*)(a_hi + byte) = make_uint2(*(uint32_t*)&h01, *(uint32_t*)&h23);
        *(uint2*)(a_lo + byte) = make_uint2(*(uint32_t*)&l01, *(uint32_t*)&l23);
    }
    // copy W^T hi/lo into padded smem (uint4 = 8 bf16)
    const uint4* wh4 = (const uint4*)g_wt_hi;
    const uint4* wl4 = (const uint4*)g_wt_lo;
#pragma unroll
    for (int i = 0; i < 8; i++) {
        int idx = i * 256 + t;             // 0..2047
        int row = idx >> 4;
        int ch  = idx & 15;
        uint32_t byte = (uint32_t)row * SPITCH_B + ch * 16;
        *(uint4*)(b_hi + byte) = wh4[idx];
        *(uint4*)(b_lo + byte) = wl4[idx];
    }
    __syncthreads();

    float acc[16][4];
#pragma unroll
    for (int n = 0; n < 16; n++)
#pragma unroll
        for (int q = 0; q < 4; q++) acc[n][q] = 0.f;

    uint32_t aHiU = smem_u32(a_hi), aLoU = smem_u32(a_lo);
    uint32_t bHiU = smem_u32(b_hi), bLoU = smem_u32(b_lo);

    int g = lane >> 3, r8 = lane & 7;
    // A: g0 rows m0..7@k0 | g1 m0+8..15@k0 | g2 m0..7@k0+8 | g3 m0+8..15@k0+8
    uint32_t aOff = (uint32_t)(wid * 16 + (g & 1) * 8 + r8) * SPITCH_B + (g >> 1) * 16;
    // B: g0 n0..7@k0 | g1 n0..7@k0+8 | g2 n0+8..15@k0 | g3 n0+8..15@k0+8
    uint32_t bOff = (uint32_t)((g >> 1) * 8 + r8) * SPITCH_B + (g & 1) * 16;

#pragma unroll
    for (int pass = 0; pass < 3; pass++) {
        uint32_t Abase = (pass == 2 ? aLoU : aHiU) + aOff;
        uint32_t Bbase = (pass == 1 ? bLoU : bHiU) + bOff;
#pragma unroll
        for (int ks = 0; ks < 8; ks++) {
            uint32_t a0, a1, a2, a3;
            ldmx4(a0, a1, a2, a3, Abase + ks * 32);
#pragma unroll
            for (int nt = 0; nt < 8; nt++) {
                uint32_t b0, b1, b2, b3;
                ldmx4(b0, b1, b2, b3, Bbase + nt * (16 * SPITCH_B) + ks * 32);
                mma_bf16(acc[2 * nt],     a0, a1, a2, a3, b0, b1);
                mma_bf16(acc[2 * nt + 1], a0, a1, a2, a3, b2, b3);
            }
        }
    }

    // epilogue: fragment-direct float2 stores
    int row0 = tileBase + wid * 16 + (lane >> 2);
    int colb = (lane & 3) * 2;
#pragma unroll
    for (int nt = 0; nt < 16; nt++) {
        int col = nt * 8 + colb;
        if (row0 < N)
            *(float2*)&g_xw[(size_t)row0 * 128 + col] = make_float2(acc[nt][0], acc[nt][1]);
        if (row0 + 8 < N)
            *(float2*)&g_xw[(size_t)(row0 + 8) * 128 + col] = make_float2(acc[nt][2], acc[nt][3]);
    }
}

// ---- fallback f32x2 GEMM (proven) ----
__global__ __launch_bounds__(256) void k_gemm(
    const float* __restrict__ x, const float* __restrict__ W, int N)
{
    __shared__ float xs_t[32][66];
    __shared__ float ws[32][128];
    int t = threadIdx.x, tx = t & 31, ty = t >> 5;
    int rowBase = blockIdx.x * 64;
    unsigned long long acc[4][4];
#pragma unroll
    for (int j = 0; j < 4; j++)
#pragma unroll
        for (int c = 0; c < 4; c++) acc[j][c] = 0ULL;
    for (int k0 = 0; k0 < 128; k0 += 32) {
        __syncthreads();
#pragma unroll
        for (int i = 0; i < 4; i++) {
            int j = t + i * 256, k = j >> 5, c = (j & 31) << 2;
            float4 v = *(const float4*)&W[(size_t)(k0 + k) * 128 + c];
            ws[k][c] = v.x; ws[k][c+1] = v.y; ws[k][c+2] = v.z; ws[k][c+3] = v.w;
        }
#pragma unroll
        for (int i = 0; i < 2; i++) {
            int j = t + i * 256, r = j >> 3, kk = (j & 7) << 2;
            int row = rowBase + r;
            float4 v = make_float4(0.f, 0.f, 0.f, 0.f);
            if (row < N) v = *(const float4*)&x[(size_t)row * 128 + k0 + kk];
            xs_t[kk][r] = v.x; xs_t[kk+1][r] = v.y; xs_t[kk+2][r] = v.z; xs_t[kk+3][r] = v.w;
        }
        __syncthreads();
#pragma unroll
        for (int k = 0; k < 32; k++) {
            float4 bv = *(const float4*)&ws[k][tx << 2];
            unsigned long long bd[4];
            asm("mov.b64 %0, {%1,%1};" : "=l"(bd[0]) : "f"(bv.x));
            asm("mov.b64 %0, {%1,%1};" : "=l"(bd[1]) : "f"(bv.y));
            asm("mov.b64 %0, {%1,%1};" : "=l"(bd[2]) : "f"(bv.z));
            asm("mov.b64 %0, {%1,%1};" : "=l"(bd[3]) : "f"(bv.w));
#pragma unroll
            for (int j = 0; j < 4; j++) {
                unsigned long long ap = *(const unsigned long long*)&xs_t[k][ty * 8 + 2 * j];
#pragma unroll
                for (int c = 0; c < 4; c++)
                    asm("fma.rn.f32x2 %0, %1, %2, %0;" : "+l"(acc[j][c]) : "l"(ap), "l"(bd[c]));
            }
        }
    }
#pragma unroll
    for (int j = 0; j < 4; j++) {
        float lo[4], hi[4];
#pragma unroll
        for (int c = 0; c < 4; c++)
            asm("mov.b64 {%0,%1}, %2;" : "=f"(lo[c]), "=f"(hi[c]) : "l"(acc[j][c]));
        int row0 = rowBase + ty * 8 + 2 * j;
        if (row0 < N)
            *(float4*)&g_xw[(size_t)row0 * 128 + (tx << 2)] = make_float4(lo[0], lo[1], lo[2], lo[3]);
        if (row0 + 1 < N)
            *(float4*)&g_xw[(size_t)(row0 + 1) * 128 + (tx << 2)] = make_float4(hi[0], hi[1], hi[2], hi[3]);
    }
}

// ---- aggregate: TWO nodes per warp, predicated interleaved gathers (R10 proven) ----
__global__ __launch_bounds__(256) void k_agg2(
    const float* __restrict__ b, float* __restrict__ out, int N)
{
    int warp = (int)((blockIdx.x * (unsigned)blockDim.x + threadIdx.x) >> 5);
    int lane = threadIdx.x & 31;
    int c0 = warp * 2;
    int c1 = warp * 2 + 1;
    if (c0 >= N) return;
    bool has1 = (c1 < N);

    int cnt0 = g_cnt[c0];
    int cnt1 = has1 ? g_cnt[c1] : 0;
    int m0 = cnt0 < CAP ? cnt0 : CAP;
    int m1 = cnt1 < CAP ? cnt1 : CAP;
    float dc0 = g_dinv[c0];
    float dc1 = has1 ? g_dinv[c1] : 0.f;
    int col = lane << 2;
    const int* bk0 = &g_bucket[(size_t)c0 * CAP];
    const int* bk1 = &g_bucket[(size_t)c1 * CAP];

    float4 a0 = make_float4(0.f, 0.f, 0.f, 0.f);
    float4 a1 = make_float4(0.f, 0.f, 0.f, 0.f);

    int mm = m0 > m1 ? m0 : m1;
    for (int j = 0; j < mm; j += 2) {
        int  i00 = (j     < m0) ? bk0[j]     : c0;
        int  i01 = (j + 1 < m0) ? bk0[j + 1] : c0;
        int  i10 = (j     < m1) ? bk1[j]     : c0;
        int  i11 = (j + 1 < m1) ? bk1[j + 1] : c0;
        float w00 = (j     < m0) ? g_dinv[i00] : 0.f;
        float w01 = (j + 1 < m0) ? g_dinv[i01] : 0.f;
        float w10 = (j     < m1) ? g_dinv[i10] : 0.f;
        float w11 = (j + 1 < m1) ? g_dinv[i11] : 0.f;
        float4 v00 = *(const float4*)&g_xw[(size_t)i00 * 128 + col];
        float4 v01 = *(const float4*)&g_xw[(size_t)i01 * 128 + col];
        float4 v10 = *(const float4*)&g_xw[(size_t)i10 * 128 + col];
        float4 v11 = *(const float4*)&g_xw[(size_t)i11 * 128 + col];
        a0.x += w00 * v00.x + w01 * v01.x;
        a0.y += w00 * v00.y + w01 * v01.y;
        a0.z += w00 * v00.z + w01 * v01.z;
        a0.w += w00 * v00.w + w01 * v01.w;
        a1.x += w10 * v10.x + w11 * v11.x;
        a1.y += w10 * v10.y + w11 * v11.y;
        a1.z += w10 * v10.z + w11 * v11.z;
        a1.w += w10 * v10.w + w11 * v11.w;
    }

    float4 bb = *(const float4*)&b[col];
    {
        float s = 2.0f * dc0 * dc0;
        float4 xwc = *(const float4*)&g_xw[(size_t)c0 * 128 + col];
        float4 o;
        o.x = fmaf(dc0, a0.x, fmaf(s, xwc.x, bb.x));
        o.y = fmaf(dc0, a0.y, fmaf(s, xwc.y, bb.y));
        o.z = fmaf(dc0, a0.z, fmaf(s, xwc.z, bb.z));
        o.w = fmaf(dc0, a0.w, fmaf(s, xwc.w, bb.w));
        *(float4*)&out[(size_t)c0 * 128 + col] = o;
    }
    if (has1) {
        float s = 2.0f * dc1 * dc1;
        float4 xwc = *(const float4*)&g_xw[(size_t)c1 * 128 + col];
        float4 o;
        o.x = fmaf(dc1, a1.x, fmaf(s, xwc.x, bb.x));
        o.y = fmaf(dc1, a1.y, fmaf(s, xwc.y, bb.y));
        o.z = fmaf(dc1, a1.z, fmaf(s, xwc.z, bb.z));
        o.w = fmaf(dc1, a1.w, fmaf(s, xwc.w, bb.w));
        *(float4*)&out[(size_t)c1 * 128 + col] = o;
    }
}

// ---------------- launch ----------------
struct Ctx {
    cudaStream_t s;
    cudaEvent_t  fork, join;
    void*        cntAddr;
    bool         ok;
};
static Ctx& ctx() {
    static Ctx c = [] {
        Ctx c{};
        c.ok = true;
        if (cudaStreamCreateWithFlags(&c.s, cudaStreamNonBlocking) != cudaSuccess) c.ok = false;
        if (cudaEventCreateWithFlags(&c.fork, cudaEventDisableTiming) != cudaSuccess) c.ok = false;
        if (cudaEventCreateWithFlags(&c.join, cudaEventDisableTiming) != cudaSuccess) c.ok = false;
        if (cudaGetSymbolAddress(&c.cntAddr, g_cnt) != cudaSuccess) c.ok = false;
        if (cudaFuncSetAttribute(k_gemm_mma, cudaFuncAttributeMaxDynamicSharedMemorySize,
                                 SMEM_MMA) != cudaSuccess) c.ok = false;
        return c;
    }();
    return c;
}

extern "C" void kernel_launch(void* const* d_in, const int* in_sizes, int n_in,
                              void* d_out, int out_size)
{
    const float* x  = (const float*)d_in[0];
    const void*  ei = (const void*)d_in[1];
    const float* W  = (const float*)d_in[2];
    const float* b  = (const float*)d_in[3];
    float* out = (float*)d_out;

    int N = in_sizes[0] / FDIM;   // 100000
    int E = in_sizes[1] / 2;      // 640000
    int nWarps = (N + 1) / 2;

    Ctx& c = ctx();

    if (c.ok) {
        cudaEventRecord(c.fork, 0);
        cudaStreamWaitEvent(c.s, c.fork, 0);
        k_prepw<<<64, 256, 0, c.s>>>(W);
        k_gemm_mma<<<(N + 127) / 128, 256, SMEM_MMA, c.s>>>(x, N);
        cudaEventRecord(c.join, c.s);

        cudaMemsetAsync(c.cntAddr, 0, (size_t)N * sizeof(int), 0);
        k_fill<<<(E + 255) / 256, 256>>>(ei, E, N);
        k_dinv<<<(N + 255) / 256, 256>>>(N);

        cudaStreamWaitEvent(0, c.join, 0);
        k_agg2<<<(nWarps * 32 + 255) / 256, 256>>>(b, out, N);
    } else {
        cudaMemsetAsync(c.cntAddr, 0, (size_t)N * sizeof(int), 0);
        k_fill<<<(E + 255) / 256, 256>>>(ei, E, N);
        k_dinv<<<(N + 255) / 256, 256>>>(N);
        k_gemm <<<(N + 63) / 64, 256>>>(x, W, N);
        k_agg2 <<<(nWarps * 32 + 255) / 256, 256>>>(b, out, N);
    }
}

// round 12
// speedup vs baseline: 1.3966x; 1.0962x over previous
#include <cuda_runtime.h>
#include <cuda_bf16.h>
#include <cstdint>

#define NMAX 100000
#define FDIM 128
#define CAP  64

// Scratch (__device__ globals; no cudaMalloc allowed)
__device__ int   g_cnt[NMAX];
__device__ float g_dinv[NMAX];
__device__ int   g_bucket[(size_t)NMAX * CAP];
__device__ float g_xw[(size_t)NMAX * FDIM];
__device__ __align__(16) __nv_bfloat16 g_wt_hi[16384];  // W^T hi [n][k]
__device__ __align__(16) __nv_bfloat16 g_wt_lo[16384];  // W^T lo [n][k]

// ---- per-block dtype detection (int64 vs silently-downcast int32) ----
__device__ __forceinline__ int detect_is64_block(const void* ei, int E, int N) {
    __shared__ int s_is64;
    if (threadIdx.x < 32) {
        int n = E < 32 ? E : 32;
        int ok = 1;
        if ((int)threadIdx.x < n) {
            long long v = ((const long long*)ei)[threadIdx.x];
            ok = (v >= 0 && v < (long long)N);
        }
        unsigned m = __ballot_sync(0xffffffffu, ok);
        if (threadIdx.x == 0) s_is64 = (m == 0xffffffffu);
    }
    __syncthreads();
    return s_is64;
}
__device__ __forceinline__ int load_idx(const void* ei, size_t i, int is64) {
    if (is64) return (int)((const long long*)ei)[i];
    return ((const int*)ei)[i];
}

__global__ void k_fill(const void* __restrict__ ei, int E, int N) {
    int is64 = detect_is64_block(ei, E, N);
    int e = blockIdx.x * blockDim.x + threadIdx.x;
    if (e < E) {
        int r = load_idx(ei, (size_t)e, is64);
        int c = load_idx(ei, (size_t)E + e, is64);
        int pos = atomicAdd(&g_cnt[c], 1);
        if (pos < CAP) g_bucket[(size_t)c * CAP + pos] = r;
    }
}

__global__ void k_dinv(int N) {
    int i = blockIdx.x * blockDim.x + threadIdx.x;
    if (i < N) g_dinv[i] = rsqrtf((float)g_cnt[i] + 2.0f);
}

// ---- prep: W^T -> bf16 hi/lo ----
__global__ void k_prepw(const float* __restrict__ W) {
    int idx = blockIdx.x * blockDim.x + threadIdx.x;   // 0..16383
    int n = idx >> 7, k = idx & 127;
    float w = W[(size_t)k * 128 + n];
    __nv_bfloat16 hi = __float2bfloat16(w);
    __nv_bfloat16 lo = __float2bfloat16(w - __bfloat162float(hi));
    g_wt_hi[n * 128 + k] = hi;
    g_wt_lo[n * 128 + k] = lo;
}

// ---- mma helpers ----
__device__ __forceinline__ uint32_t smem_u32(const void* p) {
    uint32_t a;
    asm("{ .reg .u64 t; cvta.to.shared.u64 t, %1; cvt.u32.u64 %0, t; }"
        : "=r"(a) : "l"(p));
    return a;
}
__device__ __forceinline__ void ldmx4(uint32_t& r0, uint32_t& r1, uint32_t& r2,
                                      uint32_t& r3, uint32_t addr) {
    asm volatile("ldmatrix.sync.aligned.m8n8.x4.shared.b16 {%0,%1,%2,%3}, [%4];"
                 : "=r"(r0), "=r"(r1), "=r"(r2), "=r"(r3) : "r"(addr));
}
__device__ __forceinline__ void mma_bf16(float* c, uint32_t a0, uint32_t a1,
                                         uint32_t a2, uint32_t a3,
                                         uint32_t b0, uint32_t b1) {
    asm volatile(
        "mma.sync.aligned.m16n8k16.row.col.f32.bf16.bf16.f32 "
        "{%0,%1,%2,%3}, {%4,%5,%6,%7}, {%8,%9}, {%0,%1,%2,%3};"
        : "+f"(c[0]), "+f"(c[1]), "+f"(c[2]), "+f"(c[3])
        : "r"(a0), "r"(a1), "r"(a2), "r"(a3), "r"(b0), "r"(b1));
}

// ---- tensor-core GEMM: g_xw = x @ W via 3-term bf16 split ----
// M=64 tile, 2 CTAs/SM. Warp = 16 rows x 64 cols. Fused single k-loop.
#define SPITCH_B 272                       // bytes per smem row (conflict-free ldmatrix)
#define A_ARR    (64 * SPITCH_B)           // 17408
#define B_ARR    (128 * SPITCH_B)          // 34816
#define SMEM_MMA (2 * A_ARR + 2 * B_ARR)   // 104448

__global__ __launch_bounds__(256, 2) void k_gemm_mma(const float* __restrict__ x, int N)
{
    extern __shared__ char sm[];
    char* a_hi = sm;
    char* a_lo = sm + A_ARR;
    char* b_hi = sm + 2 * A_ARR;
    char* b_lo = sm + 2 * A_ARR + B_ARR;

    int t = threadIdx.x, wid = t >> 5, lane = t & 31;
    int wm = wid & 3;                      // warp row group: rows wm*16..+15
    int wn = wid >> 2;                     // warp col half: cols wn*64..+63
    int tileBase = blockIdx.x * 64;

    // convert x tile (64x128) to bf16 hi/lo, padded rows
#pragma unroll
    for (int i = 0; i < 8; i++) {
        int widx = i * 256 + t;            // float4 index, 0..2047
        int row  = widx >> 5;
        int c4   = (widx & 31) << 2;
        int grow = tileBase + row;
        float4 v = make_float4(0.f, 0.f, 0.f, 0.f);
        if (grow < N) v = *(const float4*)(x + (size_t)grow * 128 + c4);
        __nv_bfloat16 hx = __float2bfloat16(v.x), hy = __float2bfloat16(v.y);
        __nv_bfloat16 hz = __float2bfloat16(v.z), hw = __float2bfloat16(v.w);
        __nv_bfloat16 lx = __float2bfloat16(v.x - __bfloat162float(hx));
        __nv_bfloat16 ly = __float2bfloat16(v.y - __bfloat162float(hy));
        __nv_bfloat16 lz = __float2bfloat16(v.z - __bfloat162float(hz));
        __nv_bfloat16 lw = __float2bfloat16(v.w - __bfloat162float(hw));
        __nv_bfloat162 h01(hx, hy), h23(hz, hw), l01(lx, ly), l23(lz, lw);
        uint32_t byte = (uint32_t)row * SPITCH_B + c4 * 2;
        *(uint2*)(a_hi + byte) = make_uint2(*(uint32_t*)&h01, *(uint32_t*)&h23);
        *(uint2*)(a_lo + byte) = make_uint2(*(uint32_t*)&l01, *(uint32_t*)&l23);
    }
    // copy W^T hi/lo into padded smem (uint4 = 8 bf16)
    const uint4* wh4 = (const uint4*)g_wt_hi;
    const uint4* wl4 = (const uint4*)g_wt_lo;
#pragma unroll
    for (int i = 0; i < 8; i++) {
        int idx = i * 256 + t;             // 0..2047
        int row = idx >> 4;
        int ch  = idx & 15;
        uint32_t byte = (uint32_t)row * SPITCH_B + ch * 16;
        *(uint4*)(b_hi + byte) = wh4[idx];
        *(uint4*)(b_lo + byte) = wl4[idx];
    }
    __syncthreads();

    float acc[8][4];
#pragma unroll
    for (int n = 0; n < 8; n++)
#pragma unroll
        for (int q = 0; q < 4; q++) acc[n][q] = 0.f;

    int g = lane >> 3, r8 = lane & 7;
    // A frag addr (verified R11 mapping): [m0-7,k0-7][m8-15,k0-7][m0-7,k8-15][m8-15,k8-15]
    uint32_t aHiU = smem_u32(a_hi) + (uint32_t)(wm * 16 + (g & 1) * 8 + r8) * SPITCH_B + (g >> 1) * 16;
    uint32_t aLoU = smem_u32(a_lo) + (uint32_t)(wm * 16 + (g & 1) * 8 + r8) * SPITCH_B + (g >> 1) * 16;
    // B frag addr (verified R11 mapping): rows = n within warp's 64-col half
    uint32_t bOff = (uint32_t)(wn * 64 + (g >> 1) * 8 + r8) * SPITCH_B + (g & 1) * 16;
    uint32_t bHiU = smem_u32(b_hi) + bOff;
    uint32_t bLoU = smem_u32(b_lo) + bOff;

#pragma unroll
    for (int ks = 0; ks < 8; ks++) {
        uint32_t ah0, ah1, ah2, ah3, al0, al1, al2, al3;
        ldmx4(ah0, ah1, ah2, ah3, aHiU + ks * 32);
        ldmx4(al0, al1, al2, al3, aLoU + ks * 32);
#pragma unroll
        for (int nt = 0; nt < 4; nt++) {
            uint32_t bh0, bh1, bh2, bh3;
            ldmx4(bh0, bh1, bh2, bh3, bHiU + nt * (16 * SPITCH_B) + ks * 32);
            mma_bf16(acc[2 * nt],     ah0, ah1, ah2, ah3, bh0, bh1);  // hi*hi
            mma_bf16(acc[2 * nt + 1], ah0, ah1, ah2, ah3, bh2, bh3);
            mma_bf16(acc[2 * nt],     al0, al1, al2, al3, bh0, bh1);  // lo*hi
            mma_bf16(acc[2 * nt + 1], al0, al1, al2, al3, bh2, bh3);
            uint32_t bl0, bl1, bl2, bl3;
            ldmx4(bl0, bl1, bl2, bl3, bLoU + nt * (16 * SPITCH_B) + ks * 32);
            mma_bf16(acc[2 * nt],     ah0, ah1, ah2, ah3, bl0, bl1);  // hi*lo
            mma_bf16(acc[2 * nt + 1], ah0, ah1, ah2, ah3, bl2, bl3);
        }
    }

    // epilogue: fragment-direct float2 stores
    int row0 = tileBase + wm * 16 + (lane >> 2);
    int colb = wn * 64 + (lane & 3) * 2;
#pragma unroll
    for (int nt = 0; nt < 8; nt++) {
        int col = colb + nt * 8;
        if (row0 < N)
            *(float2*)&g_xw[(size_t)row0 * 128 + col] = make_float2(acc[nt][0], acc[nt][1]);
        if (row0 + 8 < N)
            *(float2*)&g_xw[(size_t)(row0 + 8) * 128 + col] = make_float2(acc[nt][2], acc[nt][3]);
    }
}

// ---- fallback f32x2 GEMM (proven) ----
__global__ __launch_bounds__(256) void k_gemm(
    const float* __restrict__ x, const float* __restrict__ W, int N)
{
    __shared__ float xs_t[32][66];
    __shared__ float ws[32][128];
    int t = threadIdx.x, tx = t & 31, ty = t >> 5;
    int rowBase = blockIdx.x * 64;
    unsigned long long acc[4][4];
#pragma unroll
    for (int j = 0; j < 4; j++)
#pragma unroll
        for (int c = 0; c < 4; c++) acc[j][c] = 0ULL;
    for (int k0 = 0; k0 < 128; k0 += 32) {
        __syncthreads();
#pragma unroll
        for (int i = 0; i < 4; i++) {
            int j = t + i * 256, k = j >> 5, c = (j & 31) << 2;
            float4 v = *(const float4*)&W[(size_t)(k0 + k) * 128 + c];
            ws[k][c] = v.x; ws[k][c+1] = v.y; ws[k][c+2] = v.z; ws[k][c+3] = v.w;
        }
#pragma unroll
        for (int i = 0; i < 2; i++) {
            int j = t + i * 256, r = j >> 3, kk = (j & 7) << 2;
            int row = rowBase + r;
            float4 v = make_float4(0.f, 0.f, 0.f, 0.f);
            if (row < N) v = *(const float4*)&x[(size_t)row * 128 + k0 + kk];
            xs_t[kk][r] = v.x; xs_t[kk+1][r] = v.y; xs_t[kk+2][r] = v.z; xs_t[kk+3][r] = v.w;
        }
        __syncthreads();
#pragma unroll
        for (int k = 0; k < 32; k++) {
            float4 bv = *(const float4*)&ws[k][tx << 2];
            unsigned long long bd[4];
            asm("mov.b64 %0, {%1,%1};" : "=l"(bd[0]) : "f"(bv.x));
            asm("mov.b64 %0, {%1,%1};" : "=l"(bd[1]) : "f"(bv.y));
            asm("mov.b64 %0, {%1,%1};" : "=l"(bd[2]) : "f"(bv.z));
            asm("mov.b64 %0, {%1,%1};" : "=l"(bd[3]) : "f"(bv.w));
#pragma unroll
            for (int j = 0; j < 4; j++) {
                unsigned long long ap = *(const unsigned long long*)&xs_t[k][ty * 8 + 2 * j];
#pragma unroll
                for (int c = 0; c < 4; c++)
                    asm("fma.rn.f32x2 %0, %1, %2, %0;" : "+l"(acc[j][c]) : "l"(ap), "l"(bd[c]));
            }
        }
    }
#pragma unroll
    for (int j = 0; j < 4; j++) {
        float lo[4], hi[4];
#pragma unroll
        for (int c = 0; c < 4; c++)
            asm("mov.b64 {%0,%1}, %2;" : "=f"(lo[c]), "=f"(hi[c]) : "l"(acc[j][c]));
        int row0 = rowBase + ty * 8 + 2 * j;
        if (row0 < N)
            *(float4*)&g_xw[(size_t)row0 * 128 + (tx << 2)] = make_float4(lo[0], lo[1], lo[2], lo[3]);
        if (row0 + 1 < N)
            *(float4*)&g_xw[(size_t)(row0 + 1) * 128 + (tx << 2)] = make_float4(hi[0], hi[1], hi[2], hi[3]);
    }
}

// ---- aggregate: TWO nodes per warp, predicated interleaved gathers (R10 proven) ----
__global__ __launch_bounds__(256) void k_agg2(
    const float* __restrict__ b, float* __restrict__ out, int N)
{
    int warp = (int)((blockIdx.x * (unsigned)blockDim.x + threadIdx.x) >> 5);
    int lane = threadIdx.x & 31;
    int c0 = warp * 2;
    int c1 = warp * 2 + 1;
    if (c0 >= N) return;
    bool has1 = (c1 < N);

    int cnt0 = g_cnt[c0];
    int cnt1 = has1 ? g_cnt[c1] : 0;
    int m0 = cnt0 < CAP ? cnt0 : CAP;
    int m1 = cnt1 < CAP ? cnt1 : CAP;
    float dc0 = g_dinv[c0];
    float dc1 = has1 ? g_dinv[c1] : 0.f;
    int col = lane << 2;
    const int* bk0 = &g_bucket[(size_t)c0 * CAP];
    const int* bk1 = &g_bucket[(size_t)c1 * CAP];

    float4 a0 = make_float4(0.f, 0.f, 0.f, 0.f);
    float4 a1 = make_float4(0.f, 0.f, 0.f, 0.f);

    int mm = m0 > m1 ? m0 : m1;
    for (int j = 0; j < mm; j += 2) {
        int  i00 = (j     < m0) ? bk0[j]     : c0;
        int  i01 = (j + 1 < m0) ? bk0[j + 1] : c0;
        int  i10 = (j     < m1) ? bk1[j]     : c0;
        int  i11 = (j + 1 < m1) ? bk1[j + 1] : c0;
        float w00 = (j     < m0) ? g_dinv[i00] : 0.f;
        float w01 = (j + 1 < m0) ? g_dinv[i01] : 0.f;
        float w10 = (j     < m1) ? g_dinv[i10] : 0.f;
        float w11 = (j + 1 < m1) ? g_dinv[i11] : 0.f;
        float4 v00 = *(const float4*)&g_xw[(size_t)i00 * 128 + col];
        float4 v01 = *(const float4*)&g_xw[(size_t)i01 * 128 + col];
        float4 v10 = *(const float4*)&g_xw[(size_t)i10 * 128 + col];
        float4 v11 = *(const float4*)&g_xw[(size_t)i11 * 128 + col];
        a0.x += w00 * v00.x + w01 * v01.x;
        a0.y += w00 * v00.y + w01 * v01.y;
        a0.z += w00 * v00.z + w01 * v01.z;
        a0.w += w00 * v00.w + w01 * v01.w;
        a1.x += w10 * v10.x + w11 * v11.x;
        a1.y += w10 * v10.y + w11 * v11.y;
        a1.z += w10 * v10.z + w11 * v11.z;
        a1.w += w10 * v10.w + w11 * v11.w;
    }

    float4 bb = *(const float4*)&b[col];
    {
        float s = 2.0f * dc0 * dc0;
        float4 xwc = *(const float4*)&g_xw[(size_t)c0 * 128 + col];
        float4 o;
        o.x = fmaf(dc0, a0.x, fmaf(s, xwc.x, bb.x));
        o.y = fmaf(dc0, a0.y, fmaf(s, xwc.y, bb.y));
        o.z = fmaf(dc0, a0.z, fmaf(s, xwc.z, bb.z));
        o.w = fmaf(dc0, a0.w, fmaf(s, xwc.w, bb.w));
        *(float4*)&out[(size_t)c0 * 128 + col] = o;
    }
    if (has1) {
        float s = 2.0f * dc1 * dc1;
        float4 xwc = *(const float4*)&g_xw[(size_t)c1 * 128 + col];
        float4 o;
        o.x = fmaf(dc1, a1.x, fmaf(s, xwc.x, bb.x));
        o.y = fmaf(dc1, a1.y, fmaf(s, xwc.y, bb.y));
        o.z = fmaf(dc1, a1.z, fmaf(s, xwc.z, bb.z));
        o.w = fmaf(dc1, a1.w, fmaf(s, xwc.w, bb.w));
        *(float4*)&out[(size_t)c1 * 128 + col] = o;
    }
}

// ---------------- launch ----------------
struct Ctx {
    cudaStream_t s;
    cudaEvent_t  fork, join;
    void*        cntAddr;
    bool         ok;
};
static Ctx& ctx() {
    static Ctx c = [] {
        Ctx c{};
        c.ok = true;
        if (cudaStreamCreateWithFlags(&c.s, cudaStreamNonBlocking) != cudaSuccess) c.ok = false;
        if (cudaEventCreateWithFlags(&c.fork, cudaEventDisableTiming) != cudaSuccess) c.ok = false;
        if (cudaEventCreateWithFlags(&c.join, cudaEventDisableTiming) != cudaSuccess) c.ok = false;
        if (cudaGetSymbolAddress(&c.cntAddr, g_cnt) != cudaSuccess) c.ok = false;
        if (cudaFuncSetAttribute(k_gemm_mma, cudaFuncAttributeMaxDynamicSharedMemorySize,
                                 SMEM_MMA) != cudaSuccess) c.ok = false;
        return c;
    }();
    return c;
}

extern "C" void kernel_launch(void* const* d_in, const int* in_sizes, int n_in,
                              void* d_out, int out_size)
{
    const float* x  = (const float*)d_in[0];
    const void*  ei = (const void*)d_in[1];
    const float* W  = (const float*)d_in[2];
    const float* b  = (const float*)d_in[3];
    float* out = (float*)d_out;

    int N = in_sizes[0] / FDIM;   // 100000
    int E = in_sizes[1] / 2;      // 640000
    int nWarps = (N + 1) / 2;

    Ctx& c = ctx();

    if (c.ok) {
        cudaEventRecord(c.fork, 0);
        cudaStreamWaitEvent(c.s, c.fork, 0);

        // main: bucket build (enqueue first; runs parallel to side stream)
        cudaMemsetAsync(c.cntAddr, 0, (size_t)N * sizeof(int), 0);
        k_fill<<<(E + 255) / 256, 256>>>(ei, E, N);
        k_dinv<<<(N + 255) / 256, 256>>>(N);

        // side: W prep + tensor-core GEMM
        k_prepw<<<64, 256, 0, c.s>>>(W);
        k_gemm_mma<<<(N + 63) / 64, 256, SMEM_MMA, c.s>>>(x, N);
        cudaEventRecord(c.join, c.s);

        cudaStreamWaitEvent(0, c.join, 0);
        k_agg2<<<(nWarps * 32 + 255) / 256, 256>>>(b, out, N);
    } else {
        cudaMemsetAsync(c.cntAddr, 0, (size_t)N * sizeof(int), 0);
        k_fill<<<(E + 255) / 256, 256>>>(ei, E, N);
        k_dinv<<<(N + 255) / 256, 256>>>(N);
        k_gemm <<<(N + 63) / 64, 256>>>(x, W, N);
        k_agg2 <<<(nWarps * 32 + 255) / 256, 256>>>(b, out, N);
    }
}